// round 1
// baseline (speedup 1.0000x reference)
#include <cuda_runtime.h>
#include <math.h>

// ---------------------------------------------------------------------------
// Radon backprojection:
//   out[b, y, x] = sum_a lerp(sino[b, a, :], (x_c*cos(th_a) + y_c*sin(th_a) - p0)/dp)
// Strategy:
//   - prep kernel: per-angle (cos/dp, sin/dp) table + c0 = -p0/dp
//   - transpose kernel: sino[B,A,P] -> sino_t[A,P,B]  (batch innermost => float4 gather)
//   - main kernel: 1 thread per pixel, 4-batch accumulator, loop over angles
// ---------------------------------------------------------------------------

#define MAX_A 2048
#define MAX_ELEMS (8 * 1024 * 1024)   // scratch: up to 32 MB transposed sinogram

__device__ float2 g_trig[MAX_A];        // (cos/dp, sin/dp)
__device__ float  g_c0;                 // -p0/dp
__device__ float  g_sino_t[MAX_ELEMS];  // [a][p][b]

__global__ void radon_prep_kernel(const float* __restrict__ thetas,
                                  const float* __restrict__ positions,
                                  int A)
{
    int a = blockIdx.x * blockDim.x + threadIdx.x;
    float p0  = positions[0];
    float dp  = positions[1] - positions[0];
    float inv = 1.0f / dp;
    if (a < A) {
        float th = thetas[a];
        g_trig[a] = make_float2(cosf(th) * inv, sinf(th) * inv);
    }
    if (a == 0) g_c0 = -p0 * inv;
}

__global__ void radon_transpose_kernel(const float* __restrict__ sino,
                                       int BC, int A, int P)
{
    int idx = blockIdx.x * blockDim.x + threadIdx.x;
    int total = BC * A * P;
    if (idx >= total) return;
    int p = idx % P;
    int a = (idx / P) % A;
    int b = idx / (P * A);
    g_sino_t[(a * P + p) * BC + b] = sino[idx];
}

// Specialized BC == 4 path: one float4 gather per (v0, v1).
__global__ void radon_backproj4_kernel(float* __restrict__ out,
                                       int A, int P, int N)
{
    __shared__ float2 strig[MAX_A];
    for (int i = threadIdx.x; i < A; i += blockDim.x) strig[i] = g_trig[i];
    __syncthreads();

    int idx = blockIdx.x * blockDim.x + threadIdx.x;
    if (idx >= N * N) return;

    int x = idx % N;
    int y = idx / N;
    float half = 0.5f * (float)(N - 1);
    float cx = (float)x - half;
    float cy = half - (float)y;         // = -(y - half)
    float c0 = g_c0;
    int   Pm2 = P - 2;

    float4 acc = make_float4(0.f, 0.f, 0.f, 0.f);
    const float4* __restrict__ sino = (const float4*)g_sino_t;

    #pragma unroll 2
    for (int a = 0; a < A; ++a) {
        float2 tr = strig[a];
        float f  = fmaf(cx, tr.x, fmaf(cy, tr.y, c0));
        float fi = floorf(f);
        int   i0 = (int)fi;
        bool  valid = (i0 >= 0) && (i0 <= Pm2);
        int   i0c = min(max(i0, 0), Pm2);

        const float4* row = sino + a * P;
        float4 v0 = __ldg(row + i0c);
        float4 v1 = __ldg(row + i0c + 1);

        float w  = f - fi;
        float w1 = valid ? w        : 0.f;
        float w0 = valid ? 1.f - w  : 0.f;

        acc.x = fmaf(v0.x, w0, fmaf(v1.x, w1, acc.x));
        acc.y = fmaf(v0.y, w0, fmaf(v1.y, w1, acc.y));
        acc.z = fmaf(v0.z, w0, fmaf(v1.z, w1, acc.z));
        acc.w = fmaf(v0.w, w0, fmaf(v1.w, w1, acc.w));
    }

    int NN = N * N;
    out[idx]          = acc.x;
    out[idx + NN]     = acc.y;
    out[idx + 2 * NN] = acc.z;
    out[idx + 3 * NN] = acc.w;
}

// Generic fallback for arbitrary BC (scalar gathers).
__global__ void radon_backproj_generic_kernel(float* __restrict__ out,
                                              int BC, int A, int P, int N)
{
    __shared__ float2 strig[MAX_A];
    for (int i = threadIdx.x; i < A; i += blockDim.x) strig[i] = g_trig[i];
    __syncthreads();

    int idx = blockIdx.x * blockDim.x + threadIdx.x;
    if (idx >= N * N) return;

    int x = idx % N;
    int y = idx / N;
    float half = 0.5f * (float)(N - 1);
    float cx = (float)x - half;
    float cy = half - (float)y;
    float c0 = g_c0;
    int   Pm2 = P - 2;
    int   NN = N * N;

    for (int b = 0; b < BC; ++b) {
        float acc = 0.f;
        for (int a = 0; a < A; ++a) {
            float2 tr = strig[a];
            float f  = fmaf(cx, tr.x, fmaf(cy, tr.y, c0));
            float fi = floorf(f);
            int   i0 = (int)fi;
            bool  valid = (i0 >= 0) && (i0 <= Pm2);
            int   i0c = min(max(i0, 0), Pm2);
            float v0 = g_sino_t[(a * P + i0c) * BC + b];
            float v1 = g_sino_t[(a * P + i0c + 1) * BC + b];
            float w  = f - fi;
            float w1 = valid ? w       : 0.f;
            float w0 = valid ? 1.f - w : 0.f;
            acc = fmaf(v0, w0, fmaf(v1, w1, acc));
        }
        out[b * NN + idx] = acc;
    }
}

extern "C" void kernel_launch(void* const* d_in, const int* in_sizes, int n_in,
                              void* d_out, int out_size)
{
    const float* sino      = (const float*)d_in[0];
    const float* thetas    = (const float*)d_in[1];
    const float* positions = (const float*)d_in[2];
    // d_in[3] = image_size (device scalar) — N derived on host instead.

    int A  = in_sizes[1];
    int P  = in_sizes[2];
    int BC = in_sizes[0] / (A * P);
    int N  = (int)(sqrt((double)(out_size / BC)) + 0.5);

    radon_prep_kernel<<<(A + 255) / 256, 256>>>(thetas, positions, A);

    int total = BC * A * P;
    radon_transpose_kernel<<<(total + 255) / 256, 256>>>(sino, BC, A, P);

    int NN = N * N;
    float* out = (float*)d_out;
    if (BC == 4) {
        radon_backproj4_kernel<<<(NN + 255) / 256, 256>>>(out, A, P, N);
    } else {
        radon_backproj_generic_kernel<<<(NN + 255) / 256, 256>>>(out, BC, A, P, N);
    }
}

// round 2
// speedup vs baseline: 2.0910x; 2.0910x over previous
#include <cuda_runtime.h>
#include <math.h>

// ---------------------------------------------------------------------------
// Radon backprojection, 2-kernel pipeline:
//   K1: transpose sino[B,A,P] -> sino_t[A,P,B] (float4 writes) + trig table
//   K2: 1 thread per pixel, float4 (4-batch) accumulator, loop over angles
// ---------------------------------------------------------------------------

#define MAX_A 2048
#define MAX_ELEMS (8 * 1024 * 1024)

__device__ float2 g_trig[MAX_A];        // (cos/dp, sin/dp)
__device__ float  g_c0;                 // -p0/dp
__device__ float  g_sino_t[MAX_ELEMS];  // [a][p][b], b innermost (BC==4 -> float4)

// K1: transpose + trig prep fused. One thread per (a,p) site; BC==4 path
// does 4 strided coalesced reads -> one coalesced float4 write.
__global__ void radon_prep_transpose4_kernel(const float* __restrict__ sino,
                                             const float* __restrict__ thetas,
                                             const float* __restrict__ positions,
                                             int A, int P)
{
    int idx = blockIdx.x * blockDim.x + threadIdx.x;
    int AP = A * P;

    float p0  = positions[0];
    float dp  = positions[1] - positions[0];
    float inv = 1.0f / dp;

    if (idx < A) {           // first A threads also build the trig table
        float s, c;
        sincosf(thetas[idx], &s, &c);
        g_trig[idx] = make_float2(c * inv, s * inv);
    }
    if (idx == 0) g_c0 = -p0 * inv;

    if (idx < AP) {
        float4 v;
        v.x = __ldg(sino + idx);
        v.y = __ldg(sino + idx + AP);
        v.z = __ldg(sino + idx + 2 * AP);
        v.w = __ldg(sino + idx + 3 * AP);
        ((float4*)g_sino_t)[idx] = v;
    }
}

// Generic-BC prep (scalar transpose).
__global__ void radon_prep_transpose_kernel(const float* __restrict__ sino,
                                            const float* __restrict__ thetas,
                                            const float* __restrict__ positions,
                                            int BC, int A, int P)
{
    int idx = blockIdx.x * blockDim.x + threadIdx.x;
    int AP = A * P;

    float p0  = positions[0];
    float dp  = positions[1] - positions[0];
    float inv = 1.0f / dp;

    if (idx < A) {
        float s, c;
        sincosf(thetas[idx], &s, &c);
        g_trig[idx] = make_float2(c * inv, s * inv);
    }
    if (idx == 0) g_c0 = -p0 * inv;

    if (idx < AP) {
        for (int b = 0; b < BC; ++b)
            g_sino_t[idx * BC + b] = __ldg(sino + idx + b * AP);
    }
}

// K2 (BC==4): one thread per pixel, float4 gathers, angle loop unrolled x4.
__global__ void __launch_bounds__(448, 1)
radon_backproj4_kernel(float* __restrict__ out, int A, int P, int N, int NN)
{
    __shared__ float2 strig[MAX_A];
    for (int i = threadIdx.x; i < A; i += blockDim.x) strig[i] = g_trig[i];
    __syncthreads();

    int idx = blockIdx.x * blockDim.x + threadIdx.x;
    if (idx >= NN) return;

    int x = idx % N;
    int y = idx / N;
    float half = 0.5f * (float)(N - 1);
    float cx = (float)x - half;
    float cy = half - (float)y;
    float c0 = g_c0;
    int   Pm2 = P - 2;

    float4 acc = make_float4(0.f, 0.f, 0.f, 0.f);
    const float4* __restrict__ sino = (const float4*)g_sino_t;

    #pragma unroll 4
    for (int a = 0; a < A; ++a) {
        float2 tr = strig[a];
        float f  = fmaf(cx, tr.x, fmaf(cy, tr.y, c0));
        float fi = floorf(f);
        int   i0 = (int)fi;
        bool  valid = (i0 >= 0) && (i0 <= Pm2);
        int   i0c = min(max(i0, 0), Pm2);

        const float4* row = sino + a * P;
        float4 v0 = __ldg(row + i0c);
        float4 v1 = __ldg(row + i0c + 1);

        float w  = f - fi;
        float w1 = valid ? w        : 0.f;
        float w0 = valid ? 1.f - w  : 0.f;

        acc.x = fmaf(v0.x, w0, fmaf(v1.x, w1, acc.x));
        acc.y = fmaf(v0.y, w0, fmaf(v1.y, w1, acc.y));
        acc.z = fmaf(v0.z, w0, fmaf(v1.z, w1, acc.z));
        acc.w = fmaf(v0.w, w0, fmaf(v1.w, w1, acc.w));
    }

    out[idx]          = acc.x;
    out[idx + NN]     = acc.y;
    out[idx + 2 * NN] = acc.z;
    out[idx + 3 * NN] = acc.w;
}

// K2 generic BC.
__global__ void radon_backproj_generic_kernel(float* __restrict__ out,
                                              int BC, int A, int P, int N, int NN)
{
    __shared__ float2 strig[MAX_A];
    for (int i = threadIdx.x; i < A; i += blockDim.x) strig[i] = g_trig[i];
    __syncthreads();

    int idx = blockIdx.x * blockDim.x + threadIdx.x;
    if (idx >= NN) return;

    int x = idx % N;
    int y = idx / N;
    float half = 0.5f * (float)(N - 1);
    float cx = (float)x - half;
    float cy = half - (float)y;
    float c0 = g_c0;
    int   Pm2 = P - 2;

    for (int b = 0; b < BC; ++b) {
        float acc = 0.f;
        for (int a = 0; a < A; ++a) {
            float2 tr = strig[a];
            float f  = fmaf(cx, tr.x, fmaf(cy, tr.y, c0));
            float fi = floorf(f);
            int   i0 = (int)fi;
            bool  valid = (i0 >= 0) && (i0 <= Pm2);
            int   i0c = min(max(i0, 0), Pm2);
            float v0 = g_sino_t[(a * P + i0c) * BC + b];
            float v1 = g_sino_t[(a * P + i0c + 1) * BC + b];
            float w  = f - fi;
            float w1 = valid ? w       : 0.f;
            float w0 = valid ? 1.f - w : 0.f;
            acc = fmaf(v0, w0, fmaf(v1, w1, acc));
        }
        out[b * NN + idx] = acc;
    }
}

extern "C" void kernel_launch(void* const* d_in, const int* in_sizes, int n_in,
                              void* d_out, int out_size)
{
    const float* sino      = (const float*)d_in[0];
    const float* thetas    = (const float*)d_in[1];
    const float* positions = (const float*)d_in[2];

    int A  = in_sizes[1];
    int P  = in_sizes[2];
    int BC = in_sizes[0] / (A * P);
    int N  = (int)(sqrt((double)(out_size / BC)) + 0.5);
    int NN = N * N;
    float* out = (float*)d_out;

    int AP = A * P;
    if (BC == 4) {
        radon_prep_transpose4_kernel<<<(AP + 255) / 256, 256>>>(sino, thetas, positions, A, P);
        int threads = 448;                         // 14 warps/block, 1 block/SM
        int blocks  = (NN + threads - 1) / threads; // 147 for N=256
        radon_backproj4_kernel<<<blocks, threads>>>(out, A, P, N, NN);
    } else {
        radon_prep_transpose_kernel<<<(AP + 255) / 256, 256>>>(sino, thetas, positions, BC, A, P);
        radon_backproj_generic_kernel<<<(NN + 255) / 256, 256>>>(out, BC, A, P, N, NN);
    }
}